// round 1
// baseline (speedup 1.0000x reference)
#include <cuda_runtime.h>
#include <math.h>

#define B_DIM 1024
#define H_DIM 1024
#define V_OUT 50000
#define V_INP 32000
#define SRC   256

// Scratch (device globals: no allocation allowed in kernel_launch)
__device__ float g_scores[(size_t)B_DIM * V_OUT];   // gen + ptr scores
__device__ int   g_winner[V_OUT];
__device__ int   g_dest[V_INP];

// ---------------------------------------------------------------------------
// Pointer-scatter preprocessing:
//   winner[pos] = max i with inp_to_act[i]==pos   (last-update-wins for .set)
//   dest[c]     = inp_to_act[c] if c is the winner of that position, else -1
// ---------------------------------------------------------------------------
__global__ void init_winner_kernel() {
    int i = blockIdx.x * blockDim.x + threadIdx.x;
    if (i < V_OUT) g_winner[i] = -1;
}

__global__ void max_winner_kernel(const int* __restrict__ inp_to_act) {
    int i = blockIdx.x * blockDim.x + threadIdx.x;
    if (i < V_INP) atomicMax(&g_winner[inp_to_act[i]], i);
}

__global__ void make_dest_kernel(const int* __restrict__ inp_to_act) {
    int c = blockIdx.x * blockDim.x + threadIdx.x;
    if (c < V_INP) {
        int p = inp_to_act[c];
        g_dest[c] = (g_winner[p] == c) ? p : -1;
    }
}

// ---------------------------------------------------------------------------
// GEMM: g_scores[m][n] = x[m,:] . W[out_map[n],:] + b[out_map[n]]
// Also writes gen_masked[m][n] = gen - 1e6 * actionmask[m][n]
// BM=128 BN=128 BK=16, 256 threads, 8x8 per thread. fp32 FFMA (exact baseline)
// ---------------------------------------------------------------------------
#define BM 128
#define BN 128
#define BK 16
#define TM 8
#define TN 8

__global__ __launch_bounds__(256, 2)
void gemm_kernel(const float* __restrict__ x, const float* __restrict__ W,
                 const float* __restrict__ bias, const int* __restrict__ out_map,
                 const int* __restrict__ mask, float* __restrict__ gen_masked)
{
    __shared__ float Xs[BK][BM + 4];
    __shared__ float Ws[BK][BN + 4];
    __shared__ int   omap_s[BN];
    __shared__ float bias_s[BN];

    const int mtile = blockIdx.x;   // 8 m-tiles (fastest varying -> W tile L2 reuse)
    const int ntile = blockIdx.y;   // 391 n-tiles
    const int tid = threadIdx.x;
    const int tx = tid & 15;        // n direction
    const int ty = tid >> 4;        // m direction

    if (tid < BN) {
        int n = ntile * BN + tid;
        int gn = n < V_OUT ? n : (V_OUT - 1);
        int r = out_map[gn];
        omap_s[tid] = r;
        bias_s[tid] = bias[r];
    }
    __syncthreads();

    float acc[TM][TN];
#pragma unroll
    for (int i = 0; i < TM; i++)
#pragma unroll
        for (int j = 0; j < TN; j++) acc[i][j] = 0.0f;

    for (int k0 = 0; k0 < H_DIM; k0 += BK) {
        // Load X tile (transposed into Xs[k][m])
#pragma unroll
        for (int r = 0; r < 2; r++) {
            int f = tid + r * 256;        // 512 float4 loads
            int m = f >> 2, kq = f & 3;
            float4 v = *(const float4*)(&x[(size_t)(mtile * BM + m) * H_DIM + k0 + kq * 4]);
            Xs[kq * 4 + 0][m] = v.x; Xs[kq * 4 + 1][m] = v.y;
            Xs[kq * 4 + 2][m] = v.z; Xs[kq * 4 + 3][m] = v.w;
        }
        // Load W tile (gathered rows via out_map), transposed into Ws[k][n]
#pragma unroll
        for (int r = 0; r < 2; r++) {
            int f = tid + r * 256;
            int n = f >> 2, kq = f & 3;
            int row = omap_s[n];
            float4 v = *(const float4*)(&W[(size_t)row * H_DIM + k0 + kq * 4]);
            Ws[kq * 4 + 0][n] = v.x; Ws[kq * 4 + 1][n] = v.y;
            Ws[kq * 4 + 2][n] = v.z; Ws[kq * 4 + 3][n] = v.w;
        }
        __syncthreads();

#pragma unroll
        for (int k = 0; k < BK; k++) {
            float a[TM], bb[TN];
            *(float4*)&a[0]  = *(const float4*)&Xs[k][ty * TM];
            *(float4*)&a[4]  = *(const float4*)&Xs[k][ty * TM + 4];
            *(float4*)&bb[0] = *(const float4*)&Ws[k][tx * TN];
            *(float4*)&bb[4] = *(const float4*)&Ws[k][tx * TN + 4];
#pragma unroll
            for (int i = 0; i < TM; i++)
#pragma unroll
                for (int j = 0; j < TN; j++)
                    acc[i][j] = fmaf(a[i], bb[j], acc[i][j]);
        }
        __syncthreads();
    }

    // Epilogue: gen = acc + bias; write g_scores and gen_masked
#pragma unroll
    for (int i = 0; i < TM; i++) {
        int m = mtile * BM + ty * TM + i;
#pragma unroll
        for (int j = 0; j < TN; j++) {
            int n = ntile * BN + tx * TN + j;
            if (n < V_OUT) {
                float gen = acc[i][j] + bias_s[tx * TN + j];
                size_t idx = (size_t)m * V_OUT + n;
                g_scores[idx] = gen;
                gen_masked[idx] = gen - 1000000.0f * (float)mask[idx];
            }
        }
    }
}

// ---------------------------------------------------------------------------
// Pointer scatter: for each (b, s): c = ctx_ids[b][s]; d = dest[c];
// if d>=0: g_scores[b][d] += attn[b][s]
// (duplicate ctx ids within a row accumulate -> matches inpdist scatter-add)
// ---------------------------------------------------------------------------
__global__ void scatter_kernel(const float* __restrict__ attn,
                               const int* __restrict__ ctx)
{
    int b = blockIdx.x;
    int s = threadIdx.x;
    int c = ctx[b * SRC + s];
    int d = g_dest[c];
    if (d >= 0) atomicAdd(&g_scores[(size_t)b * V_OUT + d], attn[b * SRC + s]);
}

// ---------------------------------------------------------------------------
// Row softmax over V_OUT=50000: 3-pass (max, sum-exp, normalize+store).
// One 1024-thread block per row. Passes 2/3 mostly hit L2 (29 MB resident).
// ---------------------------------------------------------------------------
__device__ __forceinline__ float block_reduce(float v, bool is_max, float* red)
{
    __syncthreads();   // protect previous use of red[]
#pragma unroll
    for (int o = 16; o; o >>= 1) {
        float w = __shfl_xor_sync(0xffffffffu, v, o);
        v = is_max ? fmaxf(v, w) : (v + w);
    }
    int tid = threadIdx.x;
    if ((tid & 31) == 0) red[tid >> 5] = v;
    __syncthreads();
    if (tid < 32) {
        float w = red[tid];   // blockDim == 1024 -> exactly 32 warps
#pragma unroll
        for (int o = 16; o; o >>= 1) {
            float u = __shfl_xor_sync(0xffffffffu, w, o);
            w = is_max ? fmaxf(w, u) : (w + u);
        }
        if (tid == 0) red[0] = w;
    }
    __syncthreads();
    return red[0];
}

__global__ void softmax_kernel(float* __restrict__ probs)
{
    __shared__ float red[32];
    const int b = blockIdx.x;
    const int tid = threadIdx.x;
    const float4* row4 = (const float4*)(g_scores + (size_t)b * V_OUT);
    const int NV4 = V_OUT / 4;   // 12500 exactly

    // Pass 1: max
    float lmax = -3.4e38f;
    for (int i = tid; i < NV4; i += 1024) {
        float4 v = row4[i];
        lmax = fmaxf(lmax, fmaxf(fmaxf(v.x, v.y), fmaxf(v.z, v.w)));
    }
    float rmax = block_reduce(lmax, true, red);

    // Pass 2: sum of exp
    float lsum = 0.0f;
    for (int i = tid; i < NV4; i += 1024) {
        float4 v = row4[i];
        lsum += expf(v.x - rmax) + expf(v.y - rmax)
              + expf(v.z - rmax) + expf(v.w - rmax);
    }
    float inv = 1.0f / block_reduce(lsum, false, red);

    // Pass 3: write probs
    float4* out4 = (float4*)(probs + (size_t)b * V_OUT);
    for (int i = tid; i < NV4; i += 1024) {
        float4 v = row4[i];
        v.x = expf(v.x - rmax) * inv;
        v.y = expf(v.y - rmax) * inv;
        v.z = expf(v.z - rmax) * inv;
        v.w = expf(v.w - rmax) * inv;
        out4[i] = v;
    }
}

// ---------------------------------------------------------------------------
extern "C" void kernel_launch(void* const* d_in, const int* in_sizes, int n_in,
                              void* d_out, int out_size)
{
    const float* x    = (const float*)d_in[0];   // [B, H]
    const float* W    = (const float*)d_in[1];   // [V_OUT, H]
    const float* bias = (const float*)d_in[2];   // [V_OUT]
    const float* attn = (const float*)d_in[3];   // [B, SRC]
    const int*   ctx  = (const int*)d_in[4];     // [B, SRC]
    const int*   i2a  = (const int*)d_in[5];     // [V_INP]
    const int*   omap = (const int*)d_in[6];     // [V_OUT]
    const int*   amsk = (const int*)d_in[7];     // [B, V_OUT]

    float* probs = (float*)d_out;                          // out_probs first
    float* gmask = (float*)d_out + (size_t)B_DIM * V_OUT;  // then gen_masked

    init_winner_kernel<<<(V_OUT + 255) / 256, 256>>>();
    max_winner_kernel<<<(V_INP + 255) / 256, 256>>>(i2a);
    make_dest_kernel<<<(V_INP + 255) / 256, 256>>>(i2a);

    dim3 grid(B_DIM / BM, (V_OUT + BN - 1) / BN);   // x fastest -> W-tile L2 reuse
    gemm_kernel<<<grid, 256>>>(x, W, bias, omap, amsk, gmask);

    scatter_kernel<<<B_DIM, SRC>>>(attn, ctx);

    softmax_kernel<<<B_DIM, 1024>>>(probs);
}

// round 3
// speedup vs baseline: 2.5494x; 2.5494x over previous
#include <cuda_runtime.h>
#include <cuda_bf16.h>
#include <cstdint>
#include <math.h>

#define B_DIM 1024
#define H_DIM 1024
#define KBIG  3072           // 3 * H_DIM  (hi*hi, hi*lo, lo*hi)
#define V_OUT 50000
#define V_INP 32000
#define SRC   256
#define NPAD  50176          // 392 * 128
#define BM    256
#define BN    128
#define BK    64             // bf16 elems per chunk = 128 bytes
#define NCH   (KBIG / BK)    // 48
#define STAGES 3
#define STG_SZ 49152         // (256+128) rows * 128 B
#define B_OFF  32768         // A tile = 256*128 B

// ---------------- scratch (device globals; no runtime alloc) ----------------
__device__ float         g_scores[(size_t)B_DIM * V_OUT];
__device__ __nv_bfloat16 g_xa[(size_t)B_DIM * KBIG];   // [xhi | xhi | xlo]
__device__ __nv_bfloat16 g_wb[(size_t)NPAD * KBIG];    // [whi | wlo | whi] gathered
__device__ float         g_biasg[NPAD];
__device__ int           g_winner[V_OUT];
__device__ int           g_dest[V_INP];

// ---------------- PTX helpers -----------------------------------------------
__device__ __forceinline__ uint32_t smem_u32(const void* p) {
    uint32_t a;
    asm("{ .reg .u64 t; cvta.to.shared.u64 t, %1; cvt.u32.u64 %0, t; }" : "=r"(a) : "l"(p));
    return a;
}
#define CP16(dst, src)  asm volatile("cp.async.cg.shared.global [%0], [%1], 16;" :: "r"(dst), "l"(src))
#define CP_COMMIT()     asm volatile("cp.async.commit_group;" ::: "memory")
#define CP_WAIT(n)      asm volatile("cp.async.wait_group %0;" :: "n"(n) : "memory")
#define SWZ(b) ((b) ^ (((b) >> 3) & 0x70))

__device__ __forceinline__ void ldsm_x4(uint32_t* r, uint32_t addr) {
    asm volatile("ldmatrix.sync.aligned.m8n8.x4.shared.b16 {%0,%1,%2,%3}, [%4];"
                 : "=r"(r[0]), "=r"(r[1]), "=r"(r[2]), "=r"(r[3]) : "r"(addr));
}
__device__ __forceinline__ void ldsm_x2(uint32_t* r, uint32_t addr) {
    asm volatile("ldmatrix.sync.aligned.m8n8.x2.shared.b16 {%0,%1}, [%2];"
                 : "=r"(r[0]), "=r"(r[1]) : "r"(addr));
}
__device__ __forceinline__ void mma16816(float* d, const uint32_t* a, const uint32_t* b) {
    asm volatile("mma.sync.aligned.m16n8k16.row.col.f32.bf16.bf16.f32 "
                 "{%0,%1,%2,%3}, {%4,%5,%6,%7}, {%8,%9}, {%0,%1,%2,%3};"
                 : "+f"(d[0]), "+f"(d[1]), "+f"(d[2]), "+f"(d[3])
                 : "r"(a[0]), "r"(a[1]), "r"(a[2]), "r"(a[3]), "r"(b[0]), "r"(b[1]));
}

// ---------------- conversion kernels ----------------------------------------
__device__ __forceinline__ void split4(float4 v, uint2& hi, uint2& lo) {
    float hx = __bfloat162float(__float2bfloat16_rn(v.x));
    float hy = __bfloat162float(__float2bfloat16_rn(v.y));
    float hz = __bfloat162float(__float2bfloat16_rn(v.z));
    float hw = __bfloat162float(__float2bfloat16_rn(v.w));
    __nv_bfloat162 h0 = __floats2bfloat162_rn(v.x, v.y);
    __nv_bfloat162 h1 = __floats2bfloat162_rn(v.z, v.w);
    __nv_bfloat162 l0 = __floats2bfloat162_rn(v.x - hx, v.y - hy);
    __nv_bfloat162 l1 = __floats2bfloat162_rn(v.z - hz, v.w - hw);
    hi.x = *(uint32_t*)&h0; hi.y = *(uint32_t*)&h1;
    lo.x = *(uint32_t*)&l0; lo.y = *(uint32_t*)&l1;
}

__global__ void convert_w_kernel(const float* __restrict__ W, const float* __restrict__ b,
                                 const int* __restrict__ omap) {
    int n = blockIdx.x;
    int c = threadIdx.x * 4;
    int row = (n < V_OUT) ? omap[n] : -1;
    if (threadIdx.x == 0) g_biasg[n] = (row >= 0) ? b[row] : 0.0f;
    float4 v = make_float4(0.f, 0.f, 0.f, 0.f);
    if (row >= 0) v = *(const float4*)(W + (size_t)row * H_DIM + c);
    uint2 hi, lo; split4(v, hi, lo);
    size_t base = (size_t)n * KBIG + c;
    *(uint2*)(g_wb + base)            = hi;   // whi
    *(uint2*)(g_wb + base + H_DIM)    = lo;   // wlo
    *(uint2*)(g_wb + base + 2*H_DIM)  = hi;   // whi
}

__global__ void convert_x_kernel(const float* __restrict__ x) {
    int r = blockIdx.x;
    int c = threadIdx.x * 4;
    float4 v = *(const float4*)(x + (size_t)r * H_DIM + c);
    uint2 hi, lo; split4(v, hi, lo);
    size_t base = (size_t)r * KBIG + c;
    *(uint2*)(g_xa + base)            = hi;   // xhi
    *(uint2*)(g_xa + base + H_DIM)    = hi;   // xhi
    *(uint2*)(g_xa + base + 2*H_DIM)  = lo;   // xlo
}

// ---------------- scatter preprocessing -------------------------------------
__global__ void init_winner_kernel() {
    int i = blockIdx.x * blockDim.x + threadIdx.x;
    if (i < V_OUT) g_winner[i] = -1;
}
__global__ void max_winner_kernel(const int* __restrict__ i2a) {
    int i = blockIdx.x * blockDim.x + threadIdx.x;
    if (i < V_INP) atomicMax(&g_winner[i2a[i]], i);
}
__global__ void make_dest_kernel(const int* __restrict__ i2a) {
    int c = blockIdx.x * blockDim.x + threadIdx.x;
    if (c < V_INP) { int p = i2a[c]; g_dest[c] = (g_winner[p] == c) ? p : -1; }
}

// ---------------- HMMA GEMM --------------------------------------------------
__global__ __launch_bounds__(256, 1)
void gemm_mma_kernel(const int* __restrict__ amask, float* __restrict__ gmask) {
    extern __shared__ char dyn[];
    __shared__ float bias_s[BN];
    const uint32_t sb = smem_u32(dyn);
    const int tid  = threadIdx.x;
    const int lane = tid & 31;
    const int warp = tid >> 5;
    const int warpM = warp & 3;          // 4 warps in M
    const int warpN = warp >> 2;         // 2 warps in N
    const int mtile = blockIdx.x;        // 4  (fastest -> B-tile L2 reuse)
    const int ntile = blockIdx.y;        // 392

    if (tid < BN) bias_s[tid] = g_biasg[ntile * BN + tid];

    float acc[4][8][4];
#pragma unroll
    for (int mi = 0; mi < 4; mi++)
#pragma unroll
        for (int ni = 0; ni < 8; ni++)
#pragma unroll
            for (int q = 0; q < 4; q++) acc[mi][ni][q] = 0.0f;

    // per-lane ldmatrix row offsets (swizzle xor depends only on lane&7)
    const uint32_t sw   = (uint32_t)((lane & 7) << 4);
    const uint32_t a_hi = (uint32_t)((lane >> 4) << 4);            // x4: lanes>=16 -> +16B
    const uint32_t b_hi = (uint32_t)((((lane & 15) >> 3) & 1) << 4);  // x2: lanes 8-15 -> +16B
    uint32_t a_row[4], b_row[8];
#pragma unroll
    for (int mi = 0; mi < 4; mi++)
        a_row[mi] = (uint32_t)((warpM * 64 + mi * 16 + (lane & 15)) * 128);
#pragma unroll
    for (int ni = 0; ni < 8; ni++)
        b_row[ni] = (uint32_t)(B_OFF + (warpN * 64 + ni * 8 + (lane & 7)) * 128);

    // ---- stage loader ----
    auto load_stage = [&](int c, int st) {
        const uint32_t stb = sb + st * STG_SZ;
        const int k0 = c * BK;
#pragma unroll
        for (int i = 0; i < 8; i++) {               // A: 2048 chunks / 256 thr
            int q = i * 256 + tid, row = q >> 3, c16 = q & 7;
            uint32_t dst = stb + SWZ((uint32_t)(row * 128 + c16 * 16));
            const __nv_bfloat16* src = g_xa + (size_t)(mtile * BM + row) * KBIG + k0 + c16 * 8;
            CP16(dst, src);
        }
#pragma unroll
        for (int i = 0; i < 4; i++) {               // B: 1024 chunks
            int q = i * 256 + tid, row = q >> 3, c16 = q & 7;
            uint32_t dst = stb + B_OFF + SWZ((uint32_t)(row * 128 + c16 * 16));
            const __nv_bfloat16* src = g_wb + (size_t)(ntile * BN + row) * KBIG + k0 + c16 * 8;
            CP16(dst, src);
        }
        CP_COMMIT();
    };

    load_stage(0, 0);
    load_stage(1, 1);

    for (int c = 0; c < NCH; ++c) {
        if (c < NCH - 1) CP_WAIT(1); else CP_WAIT(0);
        __syncthreads();
        if (c + 2 < NCH) load_stage(c + 2, (c + 2) % STAGES);

        const uint32_t stb = sb + (c % STAGES) * STG_SZ;
#pragma unroll
        for (int ks = 0; ks < 4; ++ks) {
            const uint32_t kb = (uint32_t)(ks * 32);
            uint32_t af[4][4], bf[8][2];
#pragma unroll
            for (int mi = 0; mi < 4; mi++)
                ldsm_x4(af[mi], stb + a_row[mi] + ((kb + a_hi) ^ sw));
#pragma unroll
            for (int ni = 0; ni < 8; ni++)
                ldsm_x2(bf[ni], stb + b_row[ni] + ((kb + b_hi) ^ sw));
#pragma unroll
            for (int mi = 0; mi < 4; mi++)
#pragma unroll
                for (int ni = 0; ni < 8; ni++)
                    mma16816(acc[mi][ni], af[mi], bf[ni]);
        }
    }
    __syncthreads();

    // ---- epilogue: +bias -> g_scores ; mask -> gmask ----
    const int r  = lane >> 2;
    const int cp = (lane & 3) * 2;
#pragma unroll
    for (int mi = 0; mi < 4; mi++) {
        const int m0 = mtile * BM + warpM * 64 + mi * 16 + r;
#pragma unroll
        for (int ni = 0; ni < 8; ni++) {
            const int n = ntile * BN + warpN * 64 + ni * 8 + cp;
            if (n >= V_OUT) continue;
            const float b0 = bias_s[warpN * 64 + ni * 8 + cp];
            const float b1 = bias_s[warpN * 64 + ni * 8 + cp + 1];
#pragma unroll
            for (int h = 0; h < 2; h++) {           // rows m0 and m0+8
                const int m = m0 + h * 8;
                const size_t idx = (size_t)m * V_OUT + n;
                float2 g;
                g.x = acc[mi][ni][h * 2 + 0] + b0;
                g.y = acc[mi][ni][h * 2 + 1] + b1;
                int2 mv = *(const int2*)(amask + idx);
                float2 gm;
                gm.x = g.x - 1000000.0f * (float)mv.x;
                gm.y = g.y - 1000000.0f * (float)mv.y;
                *(float2*)(g_scores + idx) = g;
                *(float2*)(gmask + idx)    = gm;
            }
        }
    }
}

// ---------------- pointer scatter --------------------------------------------
__global__ void scatter_kernel(const float* __restrict__ attn, const int* __restrict__ ctx) {
    int b = blockIdx.x, s = threadIdx.x;
    int c = ctx[b * SRC + s];
    int d = g_dest[c];
    if (d >= 0) atomicAdd(&g_scores[(size_t)b * V_OUT + d], attn[b * SRC + s]);
}

// ---------------- softmax -----------------------------------------------------
__device__ __forceinline__ float block_reduce(float v, bool is_max, float* red) {
    __syncthreads();
#pragma unroll
    for (int o = 16; o; o >>= 1) {
        float w = __shfl_xor_sync(0xffffffffu, v, o);
        v = is_max ? fmaxf(v, w) : (v + w);
    }
    int tid = threadIdx.x;
    if ((tid & 31) == 0) red[tid >> 5] = v;
    __syncthreads();
    if (tid < 32) {
        float w = red[tid];
#pragma unroll
        for (int o = 16; o; o >>= 1) {
            float u = __shfl_xor_sync(0xffffffffu, w, o);
            w = is_max ? fmaxf(w, u) : (w + u);
        }
        if (tid == 0) red[0] = w;
    }
    __syncthreads();
    return red[0];
}

__global__ void softmax_kernel(float* __restrict__ probs) {
    __shared__ float red[32];
    const int b = blockIdx.x, tid = threadIdx.x;
    const float4* row4 = (const float4*)(g_scores + (size_t)b * V_OUT);
    const int NV4 = V_OUT / 4;
    float lmax = -3.4e38f;
    for (int i = tid; i < NV4; i += 1024) {
        float4 v = row4[i];
        lmax = fmaxf(lmax, fmaxf(fmaxf(v.x, v.y), fmaxf(v.z, v.w)));
    }
    float rmax = block_reduce(lmax, true, red);
    float lsum = 0.0f;
    for (int i = tid; i < NV4; i += 1024) {
        float4 v = row4[i];
        lsum += expf(v.x - rmax) + expf(v.y - rmax) + expf(v.z - rmax) + expf(v.w - rmax);
    }
    float inv = 1.0f / block_reduce(lsum, false, red);
    float4* out4 = (float4*)(probs + (size_t)b * V_OUT);
    for (int i = tid; i < NV4; i += 1024) {
        float4 v = row4[i];
        v.x = expf(v.x - rmax) * inv;
        v.y = expf(v.y - rmax) * inv;
        v.z = expf(v.z - rmax) * inv;
        v.w = expf(v.w - rmax) * inv;
        out4[i] = v;
    }
}

// -----------------------------------------------------------------------------
extern "C" void kernel_launch(void* const* d_in, const int* in_sizes, int n_in,
                              void* d_out, int out_size) {
    const float* x    = (const float*)d_in[0];
    const float* W    = (const float*)d_in[1];
    const float* bias = (const float*)d_in[2];
    const float* attn = (const float*)d_in[3];
    const int*   ctx  = (const int*)d_in[4];
    const int*   i2a  = (const int*)d_in[5];
    const int*   omap = (const int*)d_in[6];
    const int*   amsk = (const int*)d_in[7];

    float* probs = (float*)d_out;
    float* gmask = (float*)d_out + (size_t)B_DIM * V_OUT;

    static int smem_set = 0;
    if (!smem_set) {
        cudaFuncSetAttribute(gemm_mma_kernel, cudaFuncAttributeMaxDynamicSharedMemorySize,
                             STAGES * STG_SZ);
        smem_set = 1;
    }

    convert_x_kernel<<<B_DIM, 256>>>(x);
    convert_w_kernel<<<NPAD, 256>>>(W, bias, omap);

    init_winner_kernel<<<(V_OUT + 255) / 256, 256>>>();
    max_winner_kernel<<<(V_INP + 255) / 256, 256>>>(i2a);
    make_dest_kernel<<<(V_INP + 255) / 256, 256>>>(i2a);

    dim3 grid(B_DIM / BM, NPAD / BN);   // (4, 392)
    gemm_mma_kernel<<<grid, 256, STAGES * STG_SZ>>>(amsk, gmask);

    scatter_kernel<<<B_DIM, SRC>>>(attn, ctx);
    softmax_kernel<<<B_DIM, 1024>>>(probs);
}

// round 4
// speedup vs baseline: 2.5623x; 1.0051x over previous
#include <cuda_runtime.h>
#include <cuda_bf16.h>
#include <cstdint>
#include <math.h>

#define B_DIM 1024
#define H_DIM 1024
#define K2    2048           // [hi | lo]
#define V_OUT 50000
#define V_INP 32000
#define SRC   256
#define NPAD  50176          // 392 * 128
#define BM    256
#define BN    128
#define BK    64             // bf16 elems per chunk = 128 bytes
#define NCH   48             // 3 terms * 16 k-groups
#define STAGES 3
#define STG_SZ 49152         // (256+128) rows * 128 B
#define B_OFF  32768         // A tile = 256*128 B

// ---------------- scratch (device globals; no runtime alloc) ----------------
__device__ float         g_scores[(size_t)B_DIM * V_OUT];
__device__ __nv_bfloat16 g_xa[(size_t)B_DIM * K2];    // [xhi | xlo]
__device__ __nv_bfloat16 g_wb[(size_t)NPAD * K2];     // [whi | wlo] gathered
__device__ float         g_biasg[NPAD];
__device__ int           g_winner[V_OUT];
__device__ int           g_dest[V_INP];

// ---------------- PTX helpers -----------------------------------------------
__device__ __forceinline__ uint32_t smem_u32(const void* p) {
    uint32_t a;
    asm("{ .reg .u64 t; cvta.to.shared.u64 t, %1; cvt.u32.u64 %0, t; }" : "=r"(a) : "l"(p));
    return a;
}
#define CP16(dst, src)  asm volatile("cp.async.cg.shared.global [%0], [%1], 16;" :: "r"(dst), "l"(src))
#define CP_COMMIT()     asm volatile("cp.async.commit_group;" ::: "memory")
#define CP_WAIT(n)      asm volatile("cp.async.wait_group %0;" :: "n"(n) : "memory")
#define SWZ(b) ((b) ^ (((b) >> 3) & 0x70))

__device__ __forceinline__ void ldsm_x4(uint32_t* r, uint32_t addr) {
    asm volatile("ldmatrix.sync.aligned.m8n8.x4.shared.b16 {%0,%1,%2,%3}, [%4];"
                 : "=r"(r[0]), "=r"(r[1]), "=r"(r[2]), "=r"(r[3]) : "r"(addr));
}
__device__ __forceinline__ void ldsm_x2(uint32_t* r, uint32_t addr) {
    asm volatile("ldmatrix.sync.aligned.m8n8.x2.shared.b16 {%0,%1}, [%2];"
                 : "=r"(r[0]), "=r"(r[1]) : "r"(addr));
}
__device__ __forceinline__ void mma16816(float* d, const uint32_t* a, const uint32_t* b) {
    asm volatile("mma.sync.aligned.m16n8k16.row.col.f32.bf16.bf16.f32 "
                 "{%0,%1,%2,%3}, {%4,%5,%6,%7}, {%8,%9}, {%0,%1,%2,%3};"
                 : "+f"(d[0]), "+f"(d[1]), "+f"(d[2]), "+f"(d[3])
                 : "r"(a[0]), "r"(a[1]), "r"(a[2]), "r"(a[3]), "r"(b[0]), "r"(b[1]));
}

// ---------------- conversion kernels ----------------------------------------
__device__ __forceinline__ void split4(float4 v, uint2& hi, uint2& lo) {
    float hx = __bfloat162float(__float2bfloat16_rn(v.x));
    float hy = __bfloat162float(__float2bfloat16_rn(v.y));
    float hz = __bfloat162float(__float2bfloat16_rn(v.z));
    float hw = __bfloat162float(__float2bfloat16_rn(v.w));
    __nv_bfloat162 h0 = __floats2bfloat162_rn(v.x, v.y);
    __nv_bfloat162 h1 = __floats2bfloat162_rn(v.z, v.w);
    __nv_bfloat162 l0 = __floats2bfloat162_rn(v.x - hx, v.y - hy);
    __nv_bfloat162 l1 = __floats2bfloat162_rn(v.z - hz, v.w - hw);
    hi.x = *(uint32_t*)&h0; hi.y = *(uint32_t*)&h1;
    lo.x = *(uint32_t*)&l0; lo.y = *(uint32_t*)&l1;
}

__global__ void convert_x_kernel(const float* __restrict__ x) {
    int r = blockIdx.x;
    int c = threadIdx.x * 4;
    float4 v = *(const float4*)(x + (size_t)r * H_DIM + c);
    uint2 hi, lo; split4(v, hi, lo);
    size_t base = (size_t)r * K2 + c;
    *(uint2*)(g_xa + base)         = hi;
    *(uint2*)(g_xa + base + H_DIM) = lo;
}

__global__ void convert_w_kernel(const float* __restrict__ W, const float* __restrict__ b,
                                 const int* __restrict__ omap) {
    int n = blockIdx.x;
    int c = threadIdx.x * 4;
    int row = (n < V_OUT) ? omap[n] : -1;
    if (threadIdx.x == 0) g_biasg[n] = (row >= 0) ? b[row] : 0.0f;
    float4 v = make_float4(0.f, 0.f, 0.f, 0.f);
    if (row >= 0) v = *(const float4*)(W + (size_t)row * H_DIM + c);
    uint2 hi, lo; split4(v, hi, lo);
    size_t base = (size_t)n * K2 + c;
    *(uint2*)(g_wb + base)         = hi;
    *(uint2*)(g_wb + base + H_DIM) = lo;
}

// ---------------- scatter preprocessing -------------------------------------
__global__ void init_winner_kernel() {
    int i = blockIdx.x * blockDim.x + threadIdx.x;
    if (i < V_OUT) g_winner[i] = -1;
}
__global__ void max_winner_kernel(const int* __restrict__ i2a) {
    int i = blockIdx.x * blockDim.x + threadIdx.x;
    if (i < V_INP) atomicMax(&g_winner[i2a[i]], i);
}
__global__ void make_dest_kernel(const int* __restrict__ i2a) {
    int c = blockIdx.x * blockDim.x + threadIdx.x;
    if (c < V_INP) { int p = i2a[c]; g_dest[c] = (g_winner[p] == c) ? p : -1; }
}

// ---------------- HMMA GEMM --------------------------------------------------
// Virtual chunk c (0..47): g = c/3, r = c%3
//   r=0: A = xhi_g, B = whi_g      (hi*hi)
//   r=1: A = xlo_g, B = whi_g      (lo*hi, B chunk is L2-hot from r=0)
//   r=2: A = xhi_g, B = wlo_g      (hi*lo)
__global__ __launch_bounds__(256, 1)
void gemm_mma_kernel(const int* __restrict__ amask, float* __restrict__ gmask) {
    extern __shared__ char dyn[];
    __shared__ float bias_s[BN];
    const uint32_t sb = smem_u32(dyn);
    const int tid  = threadIdx.x;
    const int lane = tid & 31;
    const int warp = tid >> 5;
    const int warpM = warp & 3;          // 4 warps in M
    const int warpN = warp >> 2;         // 2 warps in N
    const int mtile = blockIdx.x;        // 4  (fastest -> B-tile L2 reuse)
    const int ntile = blockIdx.y;        // 392

    if (tid < BN) bias_s[tid] = g_biasg[ntile * BN + tid];

    float acc[4][8][4];
#pragma unroll
    for (int mi = 0; mi < 4; mi++)
#pragma unroll
        for (int ni = 0; ni < 8; ni++)
#pragma unroll
            for (int q = 0; q < 4; q++) acc[mi][ni][q] = 0.0f;

    const uint32_t sw   = (uint32_t)((lane & 7) << 4);
    const uint32_t a_hi = (uint32_t)((lane >> 4) << 4);
    const uint32_t b_hi = (uint32_t)((((lane & 15) >> 3) & 1) << 4);
    uint32_t a_row[4], b_row[8];
#pragma unroll
    for (int mi = 0; mi < 4; mi++)
        a_row[mi] = (uint32_t)((warpM * 64 + mi * 16 + (lane & 15)) * 128);
#pragma unroll
    for (int ni = 0; ni < 8; ni++)
        b_row[ni] = (uint32_t)(B_OFF + (warpN * 64 + ni * 8 + (lane & 7)) * 128);

    auto load_stage = [&](int c, int st) {
        const int g = (c * 171) >> 9;        // c / 3  (valid for c < 50)
        const int r = c - g * 3;
        const int a_k0 = ((r == 1) ? (16 + g) : g) * BK;
        const int b_k0 = ((r == 2) ? (16 + g) : g) * BK;
        const uint32_t stb = sb + st * STG_SZ;
#pragma unroll
        for (int i = 0; i < 8; i++) {               // A: 2048 16B chunks / 256 thr
            int q = i * 256 + tid, row = q >> 3, c16 = q & 7;
            uint32_t dst = stb + SWZ((uint32_t)(row * 128 + c16 * 16));
            const __nv_bfloat16* src = g_xa + (size_t)(mtile * BM + row) * K2 + a_k0 + c16 * 8;
            CP16(dst, src);
        }
#pragma unroll
        for (int i = 0; i < 4; i++) {               // B: 1024 16B chunks
            int q = i * 256 + tid, row = q >> 3, c16 = q & 7;
            uint32_t dst = stb + B_OFF + SWZ((uint32_t)(row * 128 + c16 * 16));
            const __nv_bfloat16* src = g_wb + (size_t)(ntile * BN + row) * K2 + b_k0 + c16 * 8;
            CP16(dst, src);
        }
        CP_COMMIT();
    };

    load_stage(0, 0);
    load_stage(1, 1);

    for (int c = 0; c < NCH; ++c) {
        if (c < NCH - 1) CP_WAIT(1); else CP_WAIT(0);
        __syncthreads();
        if (c + 2 < NCH) load_stage(c + 2, (c + 2) % STAGES);

        const uint32_t stb = sb + (c % STAGES) * STG_SZ;
#pragma unroll
        for (int ks = 0; ks < 4; ++ks) {
            const uint32_t kb = (uint32_t)(ks * 32);
            uint32_t af[4][4], bf[8][2];
#pragma unroll
            for (int mi = 0; mi < 4; mi++)
                ldsm_x4(af[mi], stb + a_row[mi] + ((kb + a_hi) ^ sw));
#pragma unroll
            for (int ni = 0; ni < 8; ni++)
                ldsm_x2(bf[ni], stb + b_row[ni] + ((kb + b_hi) ^ sw));
#pragma unroll
            for (int mi = 0; mi < 4; mi++)
#pragma unroll
                for (int ni = 0; ni < 8; ni++)
                    mma16816(acc[mi][ni], af[mi], bf[ni]);
        }
    }
    __syncthreads();

    // ---- epilogue: +bias -> g_scores ; mask -> gmask ----
    const int r  = lane >> 2;
    const int cp = (lane & 3) * 2;
#pragma unroll
    for (int mi = 0; mi < 4; mi++) {
        const int m0 = mtile * BM + warpM * 64 + mi * 16 + r;
#pragma unroll
        for (int ni = 0; ni < 8; ni++) {
            const int n = ntile * BN + warpN * 64 + ni * 8 + cp;
            if (n >= V_OUT) continue;
            const float b0 = bias_s[warpN * 64 + ni * 8 + cp];
            const float b1 = bias_s[warpN * 64 + ni * 8 + cp + 1];
#pragma unroll
            for (int h = 0; h < 2; h++) {
                const int m = m0 + h * 8;
                const size_t idx = (size_t)m * V_OUT + n;
                float2 g;
                g.x = acc[mi][ni][h * 2 + 0] + b0;
                g.y = acc[mi][ni][h * 2 + 1] + b1;
                int2 mv = *(const int2*)(amask + idx);
                float2 gm;
                gm.x = g.x - 1000000.0f * (float)mv.x;
                gm.y = g.y - 1000000.0f * (float)mv.y;
                *(float2*)(g_scores + idx) = g;
                *(float2*)(gmask + idx)    = gm;
            }
        }
    }
}

// ---------------- pointer scatter --------------------------------------------
__global__ void scatter_kernel(const float* __restrict__ attn, const int* __restrict__ ctx) {
    int b = blockIdx.x, s = threadIdx.x;
    int c = ctx[b * SRC + s];
    int d = g_dest[c];
    if (d >= 0) atomicAdd(&g_scores[(size_t)b * V_OUT + d], attn[b * SRC + s]);
}

// ---------------- softmax: 2 passes (online max+sum, then write) -------------
__device__ __forceinline__ void ms_merge(float& m, float& s, float m2, float s2) {
    float nm = fmaxf(m, m2);
    s = s * __expf(m - nm) + s2 * __expf(m2 - nm);
    m = nm;
}

__global__ void softmax_kernel(float* __restrict__ probs) {
    __shared__ float redm[32], reds[32];
    const int b = blockIdx.x, tid = threadIdx.x;
    const float4* row4 = (const float4*)(g_scores + (size_t)b * V_OUT);
    const int NV4 = V_OUT / 4;

    // Pass 1: online (max, sum) per thread
    float m = -3.4e38f, s = 0.0f;
    for (int i = tid; i < NV4; i += 1024) {
        float4 v = row4[i];
        float lm = fmaxf(fmaxf(v.x, v.y), fmaxf(v.z, v.w));
        float ls = __expf(v.x - lm) + __expf(v.y - lm)
                 + __expf(v.z - lm) + __expf(v.w - lm);
        ms_merge(m, s, lm, ls);
    }
    // warp reduce
#pragma unroll
    for (int o = 16; o; o >>= 1) {
        float m2 = __shfl_xor_sync(0xffffffffu, m, o);
        float s2 = __shfl_xor_sync(0xffffffffu, s, o);
        ms_merge(m, s, m2, s2);
    }
    if ((tid & 31) == 0) { redm[tid >> 5] = m; reds[tid >> 5] = s; }
    __syncthreads();
    if (tid < 32) {
        float mm = redm[tid], ss = reds[tid];
#pragma unroll
        for (int o = 16; o; o >>= 1) {
            float m2 = __shfl_xor_sync(0xffffffffu, mm, o);
            float s2 = __shfl_xor_sync(0xffffffffu, ss, o);
            ms_merge(mm, ss, m2, s2);
        }
        if (tid == 0) { redm[0] = mm; reds[0] = ss; }
    }
    __syncthreads();
    const float rmax = redm[0];
    const float inv  = 1.0f / reds[0];

    // Pass 2: write probs
    float4* out4 = (float4*)(probs + (size_t)b * V_OUT);
    for (int i = tid; i < NV4; i += 1024) {
        float4 v = row4[i];
        v.x = __expf(v.x - rmax) * inv;
        v.y = __expf(v.y - rmax) * inv;
        v.z = __expf(v.z - rmax) * inv;
        v.w = __expf(v.w - rmax) * inv;
        out4[i] = v;
    }
}

// -----------------------------------------------------------------------------
extern "C" void kernel_launch(void* const* d_in, const int* in_sizes, int n_in,
                              void* d_out, int out_size) {
    const float* x    = (const float*)d_in[0];
    const float* W    = (const float*)d_in[1];
    const float* bias = (const float*)d_in[2];
    const float* attn = (const float*)d_in[3];
    const int*   ctx  = (const int*)d_in[4];
    const int*   i2a  = (const int*)d_in[5];
    const int*   omap = (const int*)d_in[6];
    const int*   amsk = (const int*)d_in[7];

    float* probs = (float*)d_out;
    float* gmask = (float*)d_out + (size_t)B_DIM * V_OUT;

    static int smem_set = 0;
    if (!smem_set) {
        cudaFuncSetAttribute(gemm_mma_kernel, cudaFuncAttributeMaxDynamicSharedMemorySize,
                             STAGES * STG_SZ);
        smem_set = 1;
    }

    // Launch order chosen so the GEMM lands in the ncu-captured slot (#4).
    convert_x_kernel<<<B_DIM, 256>>>(x);
    convert_w_kernel<<<NPAD, 256>>>(W, bias, omap);
    init_winner_kernel<<<(V_OUT + 255) / 256, 256>>>();

    dim3 grid(B_DIM / BM, NPAD / BN);   // (4, 392)
    gemm_mma_kernel<<<grid, 256, STAGES * STG_SZ>>>(amsk, gmask);

    max_winner_kernel<<<(V_INP + 255) / 256, 256>>>(i2a);
    make_dest_kernel<<<(V_INP + 255) / 256, 256>>>(i2a);
    scatter_kernel<<<B_DIM, SRC>>>(attn, ctx);
    softmax_kernel<<<B_DIM, 1024>>>(probs);
}

// round 5
// speedup vs baseline: 2.5841x; 1.0085x over previous
#include <cuda_runtime.h>
#include <cuda_bf16.h>
#include <cstdint>
#include <math.h>

#define B_DIM 1024
#define H_DIM 1024
#define K2    2048           // [hi | lo]
#define V_OUT 50000
#define V_INP 32000
#define SRC   256
#define NPAD  50176          // 392 * 128
#define BM    256
#define BN    128
#define BK    64             // bf16 elems per chunk = 128 bytes
#define NCH   48             // 3 terms * 16 k-groups
#define STAGES 4
#define STG_SZ 49152         // (256+128) rows * 128 B
#define B_OFF  32768         // A tile = 256*128 B
#define NTHR  512

// ---------------- scratch (device globals; no runtime alloc) ----------------
__device__ float         g_scores[(size_t)B_DIM * V_OUT];
__device__ __nv_bfloat16 g_xa[(size_t)B_DIM * K2];    // [xhi | xlo]
__device__ __nv_bfloat16 g_wb[(size_t)NPAD * K2];     // [whi | wlo] gathered
__device__ float         g_biasg[NPAD];
__device__ int           g_winner[V_OUT];
__device__ int           g_dest[V_INP];

// ---------------- PTX helpers -----------------------------------------------
__device__ __forceinline__ uint32_t smem_u32(const void* p) {
    uint32_t a;
    asm("{ .reg .u64 t; cvta.to.shared.u64 t, %1; cvt.u32.u64 %0, t; }" : "=r"(a) : "l"(p));
    return a;
}
#define CP16(dst, src)  asm volatile("cp.async.cg.shared.global [%0], [%1], 16;" :: "r"(dst), "l"(src))
#define CP_COMMIT()     asm volatile("cp.async.commit_group;" ::: "memory")
#define CP_WAIT(n)      asm volatile("cp.async.wait_group %0;" :: "n"(n) : "memory")
#define SWZ(b) ((b) ^ (((b) >> 3) & 0x70))

__device__ __forceinline__ void ldsm_x4(uint32_t* r, uint32_t addr) {
    asm volatile("ldmatrix.sync.aligned.m8n8.x4.shared.b16 {%0,%1,%2,%3}, [%4];"
                 : "=r"(r[0]), "=r"(r[1]), "=r"(r[2]), "=r"(r[3]) : "r"(addr));
}
__device__ __forceinline__ void ldsm_x2(uint32_t* r, uint32_t addr) {
    asm volatile("ldmatrix.sync.aligned.m8n8.x2.shared.b16 {%0,%1}, [%2];"
                 : "=r"(r[0]), "=r"(r[1]) : "r"(addr));
}
__device__ __forceinline__ void mma16816(float* d, const uint32_t* a, const uint32_t* b) {
    asm volatile("mma.sync.aligned.m16n8k16.row.col.f32.bf16.bf16.f32 "
                 "{%0,%1,%2,%3}, {%4,%5,%6,%7}, {%8,%9}, {%0,%1,%2,%3};"
                 : "+f"(d[0]), "+f"(d[1]), "+f"(d[2]), "+f"(d[3])
                 : "r"(a[0]), "r"(a[1]), "r"(a[2]), "r"(a[3]), "r"(b[0]), "r"(b[1]));
}

// ---------------- conversion kernels ----------------------------------------
__device__ __forceinline__ void split4(float4 v, uint2& hi, uint2& lo) {
    float hx = __bfloat162float(__float2bfloat16_rn(v.x));
    float hy = __bfloat162float(__float2bfloat16_rn(v.y));
    float hz = __bfloat162float(__float2bfloat16_rn(v.z));
    float hw = __bfloat162float(__float2bfloat16_rn(v.w));
    __nv_bfloat162 h0 = __floats2bfloat162_rn(v.x, v.y);
    __nv_bfloat162 h1 = __floats2bfloat162_rn(v.z, v.w);
    __nv_bfloat162 l0 = __floats2bfloat162_rn(v.x - hx, v.y - hy);
    __nv_bfloat162 l1 = __floats2bfloat162_rn(v.z - hz, v.w - hw);
    hi.x = *(uint32_t*)&h0; hi.y = *(uint32_t*)&h1;
    lo.x = *(uint32_t*)&l0; lo.y = *(uint32_t*)&l1;
}

__global__ void convert_x_kernel(const float* __restrict__ x) {
    int r = blockIdx.x;
    int c = threadIdx.x * 4;
    float4 v = *(const float4*)(x + (size_t)r * H_DIM + c);
    uint2 hi, lo; split4(v, hi, lo);
    size_t base = (size_t)r * K2 + c;
    *(uint2*)(g_xa + base)         = hi;
    *(uint2*)(g_xa + base + H_DIM) = lo;
}

__global__ void convert_w_kernel(const float* __restrict__ W, const float* __restrict__ b,
                                 const int* __restrict__ omap) {
    int n = blockIdx.x;
    int c = threadIdx.x * 4;
    int row = (n < V_OUT) ? omap[n] : -1;
    if (threadIdx.x == 0) g_biasg[n] = (row >= 0) ? b[row] : 0.0f;
    float4 v = make_float4(0.f, 0.f, 0.f, 0.f);
    if (row >= 0) v = *(const float4*)(W + (size_t)row * H_DIM + c);
    uint2 hi, lo; split4(v, hi, lo);
    size_t base = (size_t)n * K2 + c;
    *(uint2*)(g_wb + base)         = hi;
    *(uint2*)(g_wb + base + H_DIM) = lo;
}

// ---------------- scatter preprocessing -------------------------------------
__global__ void init_winner_kernel() {
    int i = blockIdx.x * blockDim.x + threadIdx.x;
    if (i < V_OUT) g_winner[i] = -1;
}
__global__ void max_winner_kernel(const int* __restrict__ i2a) {
    int i = blockIdx.x * blockDim.x + threadIdx.x;
    if (i < V_INP) atomicMax(&g_winner[i2a[i]], i);
}
__global__ void make_dest_kernel(const int* __restrict__ i2a) {
    int c = blockIdx.x * blockDim.x + threadIdx.x;
    if (c < V_INP) { int p = i2a[c]; g_dest[c] = (g_winner[p] == c) ? p : -1; }
}

// ---------------- HMMA GEMM --------------------------------------------------
// Virtual chunk c (0..47): g = c/3, r = c%3
//   r=0: A = xhi_g, B = whi_g   r=1: A = xlo_g, B = whi_g (L2-hot)   r=2: A = xhi_g, B = wlo_g
// 512 threads: 4x4 warp grid, warp tile 64x32, 4-stage cp.async pipeline.
__global__ __launch_bounds__(NTHR, 1)
void gemm_mma_kernel(const int* __restrict__ amask, float* __restrict__ gmask) {
    extern __shared__ char dyn[];
    __shared__ float bias_s[BN];
    const uint32_t sb = smem_u32(dyn);
    const int tid  = threadIdx.x;
    const int lane = tid & 31;
    const int warp = tid >> 5;           // 0..15
    const int warpM = warp & 3;          // 4 warps in M (64 rows each)
    const int warpN = warp >> 2;         // 4 warps in N (32 cols each)
    const int mtile = blockIdx.x;        // 4 (fastest -> B-tile L2 reuse)
    const int ntile = blockIdx.y;        // 392

    if (tid < BN) bias_s[tid] = g_biasg[ntile * BN + tid];

    float acc[4][4][4];
#pragma unroll
    for (int mi = 0; mi < 4; mi++)
#pragma unroll
        for (int ni = 0; ni < 4; ni++)
#pragma unroll
            for (int q = 0; q < 4; q++) acc[mi][ni][q] = 0.0f;

    const uint32_t sw   = (uint32_t)((lane & 7) << 4);
    const uint32_t a_hi = (uint32_t)((lane >> 4) << 4);               // x4: lanes>=16 -> +16B
    const uint32_t b_hi = (uint32_t)((((lane & 15) >> 3) & 1) << 4);  // x2: lanes 8-15 -> +16B
    uint32_t a_row[4], b_row[4];
#pragma unroll
    for (int mi = 0; mi < 4; mi++)
        a_row[mi] = (uint32_t)((warpM * 64 + mi * 16 + (lane & 15)) * 128);
#pragma unroll
    for (int ni = 0; ni < 4; ni++)
        b_row[ni] = (uint32_t)(B_OFF + (warpN * 32 + ni * 8 + (lane & 7)) * 128);

    auto load_stage = [&](int c, int st) {
        const int g = (c * 171) >> 9;        // c / 3  (valid for c < 50)
        const int r = c - g * 3;
        const int a_k0 = ((r == 1) ? (16 + g) : g) * BK;
        const int b_k0 = ((r == 2) ? (16 + g) : g) * BK;
        const uint32_t stb = sb + st * STG_SZ;
#pragma unroll
        for (int i = 0; i < 4; i++) {               // A: 2048 16B chunks / 512 thr
            int q = i * NTHR + tid, row = q >> 3, c16 = q & 7;
            uint32_t dst = stb + SWZ((uint32_t)(row * 128 + c16 * 16));
            const __nv_bfloat16* src = g_xa + (size_t)(mtile * BM + row) * K2 + a_k0 + c16 * 8;
            CP16(dst, src);
        }
#pragma unroll
        for (int i = 0; i < 2; i++) {               // B: 1024 16B chunks
            int q = i * NTHR + tid, row = q >> 3, c16 = q & 7;
            uint32_t dst = stb + B_OFF + SWZ((uint32_t)(row * 128 + c16 * 16));
            const __nv_bfloat16* src = g_wb + (size_t)(ntile * BN + row) * K2 + b_k0 + c16 * 8;
            CP16(dst, src);
        }
        CP_COMMIT();
    };

    load_stage(0, 0);
    load_stage(1, 1);
    load_stage(2, 2);

    for (int c = 0; c < NCH; ++c) {
        // ensure group for chunk c has retired
        if (c < NCH - 2)      CP_WAIT(2);
        else if (c == NCH - 2) CP_WAIT(1);
        else                   CP_WAIT(0);
        __syncthreads();
        if (c + 3 < NCH) load_stage(c + 3, (c + 3) & 3);

        const uint32_t stb = sb + (c & 3) * STG_SZ;
#pragma unroll
        for (int ks = 0; ks < 4; ++ks) {
            const uint32_t kb = (uint32_t)(ks * 32);
            uint32_t af[4][4], bf[4][2];
#pragma unroll
            for (int mi = 0; mi < 4; mi++)
                ldsm_x4(af[mi], stb + a_row[mi] + ((kb + a_hi) ^ sw));
#pragma unroll
            for (int ni = 0; ni < 4; ni++)
                ldsm_x2(bf[ni], stb + b_row[ni] + ((kb + b_hi) ^ sw));
#pragma unroll
            for (int mi = 0; mi < 4; mi++)
#pragma unroll
                for (int ni = 0; ni < 4; ni++)
                    mma16816(acc[mi][ni], af[mi], bf[ni]);
        }
    }
    __syncthreads();

    // ---- epilogue: +bias -> g_scores ; mask -> gmask ----
    const int r  = lane >> 2;
    const int cp = (lane & 3) * 2;
#pragma unroll
    for (int mi = 0; mi < 4; mi++) {
        const int m0 = mtile * BM + warpM * 64 + mi * 16 + r;
#pragma unroll
        for (int ni = 0; ni < 4; ni++) {
            const int n = ntile * BN + warpN * 32 + ni * 8 + cp;
            if (n >= V_OUT) continue;
            const float b0 = bias_s[warpN * 32 + ni * 8 + cp];
            const float b1 = bias_s[warpN * 32 + ni * 8 + cp + 1];
#pragma unroll
            for (int h = 0; h < 2; h++) {
                const int m = m0 + h * 8;
                const size_t idx = (size_t)m * V_OUT + n;
                float2 g;
                g.x = acc[mi][ni][h * 2 + 0] + b0;
                g.y = acc[mi][ni][h * 2 + 1] + b1;
                int2 mv = *(const int2*)(amask + idx);
                float2 gm;
                gm.x = g.x - 1000000.0f * (float)mv.x;
                gm.y = g.y - 1000000.0f * (float)mv.y;
                *(float2*)(g_scores + idx) = g;
                *(float2*)(gmask + idx)    = gm;
            }
        }
    }
}

// ---------------- pointer scatter --------------------------------------------
__global__ void scatter_kernel(const float* __restrict__ attn, const int* __restrict__ ctx) {
    int b = blockIdx.x, s = threadIdx.x;
    int c = ctx[b * SRC + s];
    int d = g_dest[c];
    if (d >= 0) atomicAdd(&g_scores[(size_t)b * V_OUT + d], attn[b * SRC + s]);
}

// ---------------- softmax: 2 passes (online max+sum, then write) -------------
__device__ __forceinline__ void ms_merge(float& m, float& s, float m2, float s2) {
    float nm = fmaxf(m, m2);
    s = s * __expf(m - nm) + s2 * __expf(m2 - nm);
    m = nm;
}

__global__ void softmax_kernel(float* __restrict__ probs) {
    __shared__ float redm[32], reds[32];
    const int b = blockIdx.x, tid = threadIdx.x;
    const float4* row4 = (const float4*)(g_scores + (size_t)b * V_OUT);
    const int NV4 = V_OUT / 4;

    float m = -3.4e38f, s = 0.0f;
    for (int i = tid; i < NV4; i += 1024) {
        float4 v = row4[i];
        float lm = fmaxf(fmaxf(v.x, v.y), fmaxf(v.z, v.w));
        float ls = __expf(v.x - lm) + __expf(v.y - lm)
                 + __expf(v.z - lm) + __expf(v.w - lm);
        ms_merge(m, s, lm, ls);
    }
#pragma unroll
    for (int o = 16; o; o >>= 1) {
        float m2 = __shfl_xor_sync(0xffffffffu, m, o);
        float s2 = __shfl_xor_sync(0xffffffffu, s, o);
        ms_merge(m, s, m2, s2);
    }
    if ((tid & 31) == 0) { redm[tid >> 5] = m; reds[tid >> 5] = s; }
    __syncthreads();
    if (tid < 32) {
        float mm = redm[tid], ss = reds[tid];
#pragma unroll
        for (int o = 16; o; o >>= 1) {
            float m2 = __shfl_xor_sync(0xffffffffu, mm, o);
            float s2 = __shfl_xor_sync(0xffffffffu, ss, o);
            ms_merge(mm, ss, m2, s2);
        }
        if (tid == 0) { redm[0] = mm; reds[0] = ss; }
    }
    __syncthreads();
    const float rmax = redm[0];
    const float inv  = 1.0f / reds[0];

    float4* out4 = (float4*)(probs + (size_t)b * V_OUT);
    for (int i = tid; i < NV4; i += 1024) {
        float4 v = row4[i];
        v.x = __expf(v.x - rmax) * inv;
        v.y = __expf(v.y - rmax) * inv;
        v.z = __expf(v.z - rmax) * inv;
        v.w = __expf(v.w - rmax) * inv;
        out4[i] = v;
    }
}

// -----------------------------------------------------------------------------
extern "C" void kernel_launch(void* const* d_in, const int* in_sizes, int n_in,
                              void* d_out, int out_size) {
    const float* x    = (const float*)d_in[0];
    const float* W    = (const float*)d_in[1];
    const float* bias = (const float*)d_in[2];
    const float* attn = (const float*)d_in[3];
    const int*   ctx  = (const int*)d_in[4];
    const int*   i2a  = (const int*)d_in[5];
    const int*   omap = (const int*)d_in[6];
    const int*   amsk = (const int*)d_in[7];

    float* probs = (float*)d_out;
    float* gmask = (float*)d_out + (size_t)B_DIM * V_OUT;

    static int smem_set = 0;
    if (!smem_set) {
        cudaFuncSetAttribute(gemm_mma_kernel, cudaFuncAttributeMaxDynamicSharedMemorySize,
                             STAGES * STG_SZ);
        smem_set = 1;
    }

    // Launch order keeps the GEMM in the ncu-captured slot (#4).
    convert_x_kernel<<<B_DIM, 256>>>(x);
    convert_w_kernel<<<NPAD, 256>>>(W, bias, omap);
    init_winner_kernel<<<(V_OUT + 255) / 256, 256>>>();

    dim3 grid(B_DIM / BM, NPAD / BN);   // (4, 392)
    gemm_mma_kernel<<<grid, NTHR, STAGES * STG_SZ>>>(amsk, gmask);

    max_winner_kernel<<<(V_INP + 255) / 256, 256>>>(i2a);
    make_dest_kernel<<<(V_INP + 255) / 256, 256>>>(i2a);
    scatter_kernel<<<B_DIM, SRC>>>(attn, ctx);
    softmax_kernel<<<B_DIM, 1024>>>(probs);
}